// round 1
// baseline (speedup 1.0000x reference)
#include <cuda_runtime.h>

#define B_ 64
#define N_ 512
#define H_ 1024
#define E_ 4
#define BN_EPS 1e-5f

// ---------------- scratch (static device globals; no allocation) ----------------
__device__ __align__(256) float g_support[(size_t)B_ * N_ * H_];   // 134 MB
__device__ __align__(256) float g_mean_part[B_ * 8 * H_];
__device__ __align__(256) float g_sum[E_ * H_];
__device__ __align__(256) float g_ss[E_ * H_];
__device__ __align__(256) float g_scale[E_ * H_];
__device__ __align__(256) float g_shift[E_ * H_];
__device__ int g_top1[B_];

// ---------------- k0: zero per-expert accumulators (graph-replay safe) ----------
__global__ void zero_stats_kernel() {
    int i = blockIdx.x * blockDim.x + threadIdx.x;
    if (i < E_ * H_) { g_sum[i] = 0.f; g_ss[i] = 0.f; }
}

// ---------------- k1: partial column means of x over N ----------
__global__ void mean_part_kernel(const float* __restrict__ x) {
    int b = blockIdx.x, s = blockIdx.y;
    const float* xb = x + (size_t)b * N_ * H_ + (size_t)s * 64 * H_;
    for (int h = threadIdx.x; h < H_; h += blockDim.x) {
        float acc = 0.f;
        #pragma unroll 8
        for (int n = 0; n < 64; n++) acc += xb[(size_t)n * H_ + h];
        g_mean_part[(b * 8 + s) * H_ + h] = acc;
    }
}

// ---------------- k2: router scores + argmax ----------
__global__ void router_kernel(const float* __restrict__ rw, const float* __restrict__ rb) {
    int b = blockIdx.x;
    __shared__ float sred[E_][256];
    float acc[E_] = {0.f, 0.f, 0.f, 0.f};
    for (int h = threadIdx.x; h < H_; h += 256) {
        float m = 0.f;
        #pragma unroll
        for (int s = 0; s < 8; s++) m += g_mean_part[(b * 8 + s) * H_ + h];
        m *= (1.0f / (float)N_);
        #pragma unroll
        for (int e = 0; e < E_; e++) acc[e] += m * rw[h * E_ + e];
    }
    #pragma unroll
    for (int e = 0; e < E_; e++) sred[e][threadIdx.x] = acc[e];
    __syncthreads();
    for (int off = 128; off > 0; off >>= 1) {
        if (threadIdx.x < off) {
            #pragma unroll
            for (int e = 0; e < E_; e++)
                sred[e][threadIdx.x] += sred[e][threadIdx.x + off];
        }
        __syncthreads();
    }
    if (threadIdx.x == 0) {
        int best = 0;
        float bv = sred[0][0] + rb[0];
        for (int e = 1; e < E_; e++) {
            float v = sred[e][0] + rb[e];
            if (v > bv) { bv = v; best = e; }
        }
        g_top1[b] = best;
    }
}

// ---------------- k3/k4: batched SGEMM, 128x128 tile, 8x8 microtile ----------
// C[bz] = A[bz] (MxK) * B[sel] (KxN); sel = top1[bz] if useTop1 else bz.
__global__ __launch_bounds__(256, 2)
void sgemm128_kernel(const float* __restrict__ Abase, long strideA, int lda,
                     const float* __restrict__ Bbase, long strideB, int ldb, int useTop1,
                     float* __restrict__ Cbase, long strideC, int ldc, int K) {
    int bz = blockIdx.z;
    const float* A = Abase + (long)bz * strideA;
    const float* Bm = Bbase + (long)(useTop1 ? g_top1[bz] : bz) * strideB;
    float* C = Cbase + (long)bz * strideC;
    int n0 = blockIdx.x * 128;
    int m0 = blockIdx.y * 128;

    __shared__ float As[8][128];
    __shared__ float Bs[8][128];

    int tid = threadIdx.x;
    int tx = tid & 15;        // 0..15 -> 8 cols each
    int ty = tid >> 4;        // 0..15 -> 8 rows each

    float acc[8][8];
    #pragma unroll
    for (int i = 0; i < 8; i++)
        #pragma unroll
        for (int j = 0; j < 8; j++) acc[i][j] = 0.f;

    int ar = tid >> 1, ac = (tid & 1) * 4;     // A: 128 rows x 8 cols, float4 each
    int br = tid >> 5, bc = (tid & 31) * 4;    // B: 8 rows x 128 cols, float4 each

    const float* Aptr = A + (long)(m0 + ar) * lda + ac;
    const float* Bptr = Bm + (long)br * ldb + n0 + bc;

    for (int k0 = 0; k0 < K; k0 += 8) {
        float4 av = *(const float4*)(Aptr + k0);
        float4 bv = *(const float4*)(Bptr + (long)k0 * ldb);
        As[ac + 0][ar] = av.x;
        As[ac + 1][ar] = av.y;
        As[ac + 2][ar] = av.z;
        As[ac + 3][ar] = av.w;
        *(float4*)&Bs[br][bc] = bv;
        __syncthreads();

        #pragma unroll
        for (int kk = 0; kk < 8; kk++) {
            float a[8], bb[8];
            *(float4*)(a)     = *(const float4*)&As[kk][ty * 8];
            *(float4*)(a + 4) = *(const float4*)&As[kk][ty * 8 + 4];
            *(float4*)(bb)     = *(const float4*)&Bs[kk][tx * 8];
            *(float4*)(bb + 4) = *(const float4*)&Bs[kk][tx * 8 + 4];
            #pragma unroll
            for (int i = 0; i < 8; i++)
                #pragma unroll
                for (int j = 0; j < 8; j++)
                    acc[i][j] += a[i] * bb[j];
        }
        __syncthreads();
    }

    #pragma unroll
    for (int i = 0; i < 8; i++) {
        float* crow = C + (long)(m0 + ty * 8 + i) * ldc + n0 + tx * 8;
        *(float4*)(crow)     = make_float4(acc[i][0], acc[i][1], acc[i][2], acc[i][3]);
        *(float4*)(crow + 4) = make_float4(acc[i][4], acc[i][5], acc[i][6], acc[i][7]);
    }
}

// ---------------- k5: per-expert BN statistics (sum, sumsq) ----------
__global__ void stats_kernel(const float* __restrict__ out) {
    int b = blockIdx.x;
    int h = blockIdx.y * 256 + threadIdx.x;
    int e = g_top1[b];
    const float* ob = out + (size_t)b * N_ * H_ + h;
    float s = 0.f, ss = 0.f;
    #pragma unroll 4
    for (int n = 0; n < N_; n++) {
        float v = ob[(size_t)n * H_];
        s += v;
        ss += v * v;
    }
    atomicAdd(&g_sum[e * H_ + h], s);
    atomicAdd(&g_ss[e * H_ + h], ss);
}

// ---------------- k6: finalize BN scale/shift ----------
__global__ void finalize_kernel(const float* __restrict__ gamma, const float* __restrict__ beta) {
    int e = blockIdx.x, h = threadIdx.x;   // grid E_, block H_
    int cg = 0;
    for (int b = 0; b < B_; b++) cg += (g_top1[b] == e);
    float cnt = fmaxf((float)cg * (float)N_, 1.0f);
    float mean = g_sum[e * H_ + h] / cnt;
    float var = g_ss[e * H_ + h] / cnt - mean * mean;
    float inv = rsqrtf(var + BN_EPS);
    float sc = gamma[e * H_ + h] * inv;
    g_scale[e * H_ + h] = sc;
    g_shift[e * H_ + h] = beta[e * H_ + h] - mean * sc;
}

// ---------------- k7: apply BN + ReLU in place ----------
__global__ void bn_relu_kernel(float* __restrict__ out) {
    size_t idx = ((size_t)blockIdx.x * blockDim.x + threadIdx.x) * 4;
    int b = (int)(idx / ((size_t)N_ * H_));
    int h = (int)(idx % H_);
    int e = g_top1[b];
    float4 v = *(float4*)(out + idx);
    float4 sc = *(const float4*)&g_scale[e * H_ + h];
    float4 sh = *(const float4*)&g_shift[e * H_ + h];
    v.x = fmaxf(v.x * sc.x + sh.x, 0.f);
    v.y = fmaxf(v.y * sc.y + sh.y, 0.f);
    v.z = fmaxf(v.z * sc.z + sh.z, 0.f);
    v.w = fmaxf(v.w * sc.w + sh.w, 0.f);
    *(float4*)(out + idx) = v;
}

// ---------------- launcher ----------------
extern "C" void kernel_launch(void* const* d_in, const int* in_sizes, int n_in,
                              void* d_out, int out_size) {
    (void)in_sizes; (void)n_in; (void)out_size;
    const float* x        = (const float*)d_in[0];   // [B,N,H]
    const float* adj      = (const float*)d_in[1];   // [B,N,N]
    const float* router_w = (const float*)d_in[2];   // [H,E]
    const float* router_b = (const float*)d_in[3];   // [E]
    const float* expert_w = (const float*)d_in[4];   // [E,H,H]
    const float* bn_gamma = (const float*)d_in[5];   // [E,H]
    const float* bn_beta  = (const float*)d_in[6];   // [E,H]
    float* out = (float*)d_out;                      // [B,N,H]

    float* support = nullptr;
    cudaGetSymbolAddress((void**)&support, g_support);

    zero_stats_kernel<<<16, 256>>>();
    mean_part_kernel<<<dim3(B_, 8), 256>>>(x);
    router_kernel<<<B_, 256>>>(router_w, router_b);

    // support[b] = x[b] (512x1024) @ expert_w[top1[b]] (1024x1024)
    sgemm128_kernel<<<dim3(H_ / 128, N_ / 128, B_), 256>>>(
        x, (long)N_ * H_, H_,
        expert_w, (long)H_ * H_, H_, 1,
        support, (long)N_ * H_, H_, H_);

    // out[b] = adj[b] (512x512) @ support[b] (512x1024)
    sgemm128_kernel<<<dim3(H_ / 128, N_ / 128, B_), 256>>>(
        adj, (long)N_ * N_, N_,
        support, (long)N_ * H_, H_, 0,
        out, (long)N_ * H_, H_, N_);

    stats_kernel<<<dim3(B_, H_ / 256), 256>>>(out);
    finalize_kernel<<<E_, H_>>>(bn_gamma, bn_beta);

    size_t total4 = (size_t)B_ * N_ * H_ / 4;
    bn_relu_kernel<<<(unsigned)(total4 / 256), 256>>>(out);
}

// round 3
// speedup vs baseline: 2.1659x; 2.1659x over previous
#include <cuda_runtime.h>
#include <cuda_bf16.h>
#include <cstdint>

#define B_ 64
#define N_ 512
#define H_ 1024
#define E_ 4
#define BN_EPS 1e-5f

// GEMM tile config
#define BM 128
#define BNT 128
#define BKK 32
#define GT 256

// SMEM: per buffer: Ahi 8K | Alo 8K | Bhi 8K | Blo 8K = 32K; double buffered = 64K
#define BUF_BYTES 32768
#define OFF_ALO 8192
#define OFF_BHI 16384
#define OFF_BLO 24576
#define SMEM_BYTES (2 * BUF_BYTES)

// ---------------- scratch (static device globals; no allocation) ----------------
__device__ __align__(256) float g_support[(size_t)B_ * N_ * H_];
__device__ __align__(256) float g_mean_part[B_ * 8 * H_];
__device__ __align__(256) float g_sum[E_ * H_];
__device__ __align__(256) float g_ss[E_ * H_];
__device__ __align__(256) float g_scale[E_ * H_];
__device__ __align__(256) float g_shift[E_ * H_];
__device__ int g_top1[B_];

// ---------------- PTX helpers (base-family ISA only; no tcgen05) ----------------
__device__ __forceinline__ uint32_t smem_u32(const void* p) {
    uint32_t a;
    asm("{ .reg .u64 t; cvta.to.shared.u64 t, %1; cvt.u32.u64 %0, t; }" : "=r"(a) : "l"(p));
    return a;
}
__device__ __forceinline__ void ldsm_x4(uint32_t (&r)[4], uint32_t addr) {
    asm volatile("ldmatrix.sync.aligned.m8n8.x4.shared.b16 {%0,%1,%2,%3}, [%4];"
        : "=r"(r[0]), "=r"(r[1]), "=r"(r[2]), "=r"(r[3]) : "r"(addr));
}
__device__ __forceinline__ void ldsm_x4_t(uint32_t (&r)[4], uint32_t addr) {
    asm volatile("ldmatrix.sync.aligned.m8n8.x4.trans.shared.b16 {%0,%1,%2,%3}, [%4];"
        : "=r"(r[0]), "=r"(r[1]), "=r"(r[2]), "=r"(r[3]) : "r"(addr));
}
__device__ __forceinline__ void mma_bf16(float (&c)[4], const uint32_t (&a)[4], const uint32_t* b) {
    asm volatile(
        "mma.sync.aligned.m16n8k16.row.col.f32.bf16.bf16.f32 "
        "{%0,%1,%2,%3}, {%4,%5,%6,%7}, {%8,%9}, {%0,%1,%2,%3};"
        : "+f"(c[0]), "+f"(c[1]), "+f"(c[2]), "+f"(c[3])
        : "r"(a[0]), "r"(a[1]), "r"(a[2]), "r"(a[3]), "r"(b[0]), "r"(b[1]));
}

// ---------------- k0: zero accumulators ----------
__global__ void zero_stats_kernel() {
    int i = blockIdx.x * blockDim.x + threadIdx.x;
    if (i < E_ * H_) { g_sum[i] = 0.f; g_ss[i] = 0.f; }
}

// ---------------- k1: partial column means of x over N ----------
__global__ void mean_part_kernel(const float* __restrict__ x) {
    int b = blockIdx.x, s = blockIdx.y;
    const float* xb = x + (size_t)b * N_ * H_ + (size_t)s * 64 * H_;
    for (int h = threadIdx.x; h < H_; h += blockDim.x) {
        float acc = 0.f;
        #pragma unroll 8
        for (int n = 0; n < 64; n++) acc += xb[(size_t)n * H_ + h];
        g_mean_part[(b * 8 + s) * H_ + h] = acc;
    }
}

// ---------------- k2: router + argmax ----------
__global__ void router_kernel(const float* __restrict__ rw, const float* __restrict__ rb) {
    int b = blockIdx.x;
    __shared__ float sred[E_][256];
    float acc[E_] = {0.f, 0.f, 0.f, 0.f};
    for (int h = threadIdx.x; h < H_; h += 256) {
        float m = 0.f;
        #pragma unroll
        for (int s = 0; s < 8; s++) m += g_mean_part[(b * 8 + s) * H_ + h];
        m *= (1.0f / (float)N_);
        #pragma unroll
        for (int e = 0; e < E_; e++) acc[e] += m * rw[h * E_ + e];
    }
    #pragma unroll
    for (int e = 0; e < E_; e++) sred[e][threadIdx.x] = acc[e];
    __syncthreads();
    for (int off = 128; off > 0; off >>= 1) {
        if (threadIdx.x < off) {
            #pragma unroll
            for (int e = 0; e < E_; e++) sred[e][threadIdx.x] += sred[e][threadIdx.x + off];
        }
        __syncthreads();
    }
    if (threadIdx.x == 0) {
        int best = 0;
        float bv = sred[0][0] + rb[0];
        for (int e = 1; e < E_; e++) {
            float v = sred[e][0] + rb[e];
            if (v > bv) { bv = v; best = e; }
        }
        g_top1[b] = best;
    }
}

// ---------------- batched bf16x3 mma.sync GEMM ----------------
// C[bz](MxNglob) = A[bz](MxK, k-contig) * B[sel](KxNglob, n-contig)
__global__ __launch_bounds__(GT, 1)
void mma_gemm_kernel(const float* __restrict__ Abase, long strideA, int lda,
                     const float* __restrict__ Bbase, long strideB, int ldb, int useTop1,
                     float* __restrict__ Cbase, long strideC, int ldc, int K) {
    extern __shared__ __align__(128) char smem[];
    const int tid = threadIdx.x;
    const int lane = tid & 31, wid = tid >> 5;
    const int bz = blockIdx.z;
    const int m0 = blockIdx.y * BM, n0 = blockIdx.x * BNT;
    const int wm = (wid >> 2) * 64, wn = (wid & 3) * 32;

    const float* A = Abase + (long)bz * strideA;
    const float* Bg = Bbase + (long)(useTop1 ? g_top1[bz] : bz) * strideB;
    float* C = Cbase + (long)bz * strideC;

    const uint32_t sb = smem_u32(smem);

    // gmem staging roles
    const int ar = tid >> 1, ahalf = tid & 1;   // A: row 0..127, k half (16 floats)
    const int bk = tid >> 3, bh = tid & 7;      // B: k row 0..31, 16-float n chunk
    const float* Aptr = A + (long)(m0 + ar) * lda + ahalf * 16;
    const float* Bptr = Bg + (long)bk * ldb + n0 + bh * 16;

    float acc[4][4][4];
    #pragma unroll
    for (int a = 0; a < 4; a++)
        #pragma unroll
        for (int b2 = 0; b2 < 4; b2++)
            #pragma unroll
            for (int c = 0; c < 4; c++) acc[a][b2][c] = 0.f;

    float fa[16], fb[16];

    auto load_tile = [&](int i) {
        const float4* p = (const float4*)(Aptr + (long)i * BKK);
        #pragma unroll
        for (int q = 0; q < 4; q++) *(float4*)&fa[q * 4] = p[q];
        const float4* pb = (const float4*)(Bptr + (long)i * BKK * ldb);
        #pragma unroll
        for (int q = 0; q < 4; q++) *(float4*)&fb[q * 4] = pb[q];
    };

    auto sts_tile = [&](int buf) {
        char* base = smem + buf * BUF_BYTES;
        // A: row ar, two 16B chunks (8 bf16 each) at chunk ids 2*ahalf, 2*ahalf+1
        #pragma unroll
        for (int cc = 0; cc < 2; cc++) {
            uint4 hw, lw;
            uint32_t* hwp = (uint32_t*)&hw;
            uint32_t* lwp = (uint32_t*)&lw;
            #pragma unroll
            for (int j = 0; j < 4; j++) {
                float x0 = fa[cc * 8 + 2 * j], x1 = fa[cc * 8 + 2 * j + 1];
                __nv_bfloat162 h2 = __floats2bfloat162_rn(x0, x1);
                float h0 = __bfloat162float(h2.x);
                float h1 = __bfloat162float(h2.y);
                __nv_bfloat162 l2 = __floats2bfloat162_rn(x0 - h0, x1 - h1);
                hwp[j] = *(uint32_t*)&h2;
                lwp[j] = *(uint32_t*)&l2;
            }
            int c = 2 * ahalf + cc;
            uint32_t off = (uint32_t)(ar * 64 + ((c ^ ((ar >> 1) & 3)) << 4));
            *(uint4*)(base + off) = hw;
            *(uint4*)(base + OFF_ALO + off) = lw;
        }
        // B: k row bk, chunk ids 2*bh, 2*bh+1
        #pragma unroll
        for (int cc = 0; cc < 2; cc++) {
            uint4 hw, lw;
            uint32_t* hwp = (uint32_t*)&hw;
            uint32_t* lwp = (uint32_t*)&lw;
            #pragma unroll
            for (int j = 0; j < 4; j++) {
                float x0 = fb[cc * 8 + 2 * j], x1 = fb[cc * 8 + 2 * j + 1];
                __nv_bfloat162 h2 = __floats2bfloat162_rn(x0, x1);
                float h0 = __bfloat162float(h2.x);
                float h1 = __bfloat162float(h2.y);
                __nv_bfloat162 l2 = __floats2bfloat162_rn(x0 - h0, x1 - h1);
                hwp[j] = *(uint32_t*)&h2;
                lwp[j] = *(uint32_t*)&l2;
            }
            int nc = 2 * bh + cc;
            uint32_t off = (uint32_t)(bk * 256 + ((nc ^ (bk & 7)) << 4));
            *(uint4*)(base + OFF_BHI + off) = hw;
            *(uint4*)(base + OFF_BLO + off) = lw;
        }
    };

    auto mma_tile = [&](int buf) {
        const uint32_t aB = sb + buf * BUF_BYTES;
        const uint32_t bB = aB + OFF_BHI;
        #pragma unroll
        for (int ks = 0; ks < 2; ks++) {
            const int kk = ks * 16;
            uint32_t ahf[4][4], alf[4][4];
            #pragma unroll
            for (int mt = 0; mt < 4; mt++) {
                int r = wm + mt * 16 + (lane & 15);
                int c = (kk >> 3) + (lane >> 4);
                uint32_t off = (uint32_t)(r * 64 + ((c ^ ((r >> 1) & 3)) << 4));
                ldsm_x4(ahf[mt], aB + off);
                ldsm_x4(alf[mt], aB + OFF_ALO + off);
            }
            uint32_t bhf[4][2], blf[4][2];
            #pragma unroll
            for (int nt = 0; nt < 2; nt++) {
                int k = kk + (lane & 15);
                int n = wn + nt * 16 + ((lane >> 4) << 3);
                int nc = n >> 3;
                uint32_t off = (uint32_t)(k * 256 + ((nc ^ (k & 7)) << 4));
                uint32_t r4[4];
                ldsm_x4_t(r4, bB + off);
                bhf[nt * 2][0] = r4[0]; bhf[nt * 2][1] = r4[1];
                bhf[nt * 2 + 1][0] = r4[2]; bhf[nt * 2 + 1][1] = r4[3];
                ldsm_x4_t(r4, bB + (OFF_BLO - OFF_BHI) + off);
                blf[nt * 2][0] = r4[0]; blf[nt * 2][1] = r4[1];
                blf[nt * 2 + 1][0] = r4[2]; blf[nt * 2 + 1][1] = r4[3];
            }
            #pragma unroll
            for (int mt = 0; mt < 4; mt++)
                #pragma unroll
                for (int n8 = 0; n8 < 4; n8++) {
                    mma_bf16(acc[mt][n8], ahf[mt], bhf[n8]);
                    mma_bf16(acc[mt][n8], ahf[mt], blf[n8]);
                    mma_bf16(acc[mt][n8], alf[mt], bhf[n8]);
                }
        }
    };

    const int nk = K / BKK;
    load_tile(0);
    sts_tile(0);
    __syncthreads();

    for (int i = 0; i < nk; i++) {
        if (i + 1 < nk) load_tile(i + 1);
        mma_tile(i & 1);
        if (i + 1 < nk) sts_tile((i + 1) & 1);
        __syncthreads();
    }

    // epilogue: direct float2 stores
    #pragma unroll
    for (int mt = 0; mt < 4; mt++) {
        int row0 = m0 + wm + mt * 16 + (lane >> 2);
        #pragma unroll
        for (int n8 = 0; n8 < 4; n8++) {
            int col = n0 + wn + n8 * 8 + (lane & 3) * 2;
            float2 v0 = make_float2(acc[mt][n8][0], acc[mt][n8][1]);
            float2 v1 = make_float2(acc[mt][n8][2], acc[mt][n8][3]);
            *(float2*)(C + (long)row0 * ldc + col) = v0;
            *(float2*)(C + (long)(row0 + 8) * ldc + col) = v1;
        }
    }
}

// ---------------- k5: per-expert BN statistics ----------
__global__ void stats_kernel(const float* __restrict__ out) {
    int b = blockIdx.x;
    int h = blockIdx.y * 256 + threadIdx.x;
    int e = g_top1[b];
    const float* ob = out + (size_t)b * N_ * H_ + h;
    float s = 0.f, ss = 0.f;
    #pragma unroll 4
    for (int n = 0; n < N_; n++) {
        float v = ob[(size_t)n * H_];
        s += v;
        ss += v * v;
    }
    atomicAdd(&g_sum[e * H_ + h], s);
    atomicAdd(&g_ss[e * H_ + h], ss);
}

// ---------------- k6: finalize BN scale/shift ----------
__global__ void finalize_kernel(const float* __restrict__ gamma, const float* __restrict__ beta) {
    int e = blockIdx.x, h = threadIdx.x;
    int cg = 0;
    for (int b = 0; b < B_; b++) cg += (g_top1[b] == e);
    float cnt = fmaxf((float)cg * (float)N_, 1.0f);
    float mean = g_sum[e * H_ + h] / cnt;
    float var = g_ss[e * H_ + h] / cnt - mean * mean;
    float inv = rsqrtf(var + BN_EPS);
    float sc = gamma[e * H_ + h] * inv;
    g_scale[e * H_ + h] = sc;
    g_shift[e * H_ + h] = beta[e * H_ + h] - mean * sc;
}

// ---------------- k7: apply BN + ReLU in place ----------
__global__ void bn_relu_kernel(float* __restrict__ out) {
    size_t idx = ((size_t)blockIdx.x * blockDim.x + threadIdx.x) * 4;
    int b = (int)(idx / ((size_t)N_ * H_));
    int h = (int)(idx % H_);
    int e = g_top1[b];
    float4 v = *(float4*)(out + idx);
    float4 sc = *(const float4*)&g_scale[e * H_ + h];
    float4 sh = *(const float4*)&g_shift[e * H_ + h];
    v.x = fmaxf(v.x * sc.x + sh.x, 0.f);
    v.y = fmaxf(v.y * sc.y + sh.y, 0.f);
    v.z = fmaxf(v.z * sc.z + sh.z, 0.f);
    v.w = fmaxf(v.w * sc.w + sh.w, 0.f);
    *(float4*)(out + idx) = v;
}

// ---------------- launcher ----------------
extern "C" void kernel_launch(void* const* d_in, const int* in_sizes, int n_in,
                              void* d_out, int out_size) {
    (void)in_sizes; (void)n_in; (void)out_size;
    const float* x        = (const float*)d_in[0];   // [B,N,H]
    const float* adj      = (const float*)d_in[1];   // [B,N,N]
    const float* router_w = (const float*)d_in[2];   // [H,E]
    const float* router_b = (const float*)d_in[3];   // [E]
    const float* expert_w = (const float*)d_in[4];   // [E,H,H]
    const float* bn_gamma = (const float*)d_in[5];   // [E,H]
    const float* bn_beta  = (const float*)d_in[6];   // [E,H]
    float* out = (float*)d_out;                      // [B,N,H]

    float* support = nullptr;
    cudaGetSymbolAddress((void**)&support, g_support);

    cudaFuncSetAttribute(mma_gemm_kernel, cudaFuncAttributeMaxDynamicSharedMemorySize, SMEM_BYTES);

    zero_stats_kernel<<<16, 256>>>();
    mean_part_kernel<<<dim3(B_, 8), 256>>>(x);
    router_kernel<<<B_, 256>>>(router_w, router_b);

    // support[b] = x[b] (512x1024) @ expert_w[top1[b]] (1024x1024)
    mma_gemm_kernel<<<dim3(H_ / BNT, N_ / BM, B_), GT, SMEM_BYTES>>>(
        x, (long)N_ * H_, H_,
        expert_w, (long)H_ * H_, H_, 1,
        support, (long)N_ * H_, H_, H_);

    // out[b] = adj[b] (512x512) @ support[b] (512x1024)
    mma_gemm_kernel<<<dim3(H_ / BNT, N_ / BM, B_), GT, SMEM_BYTES>>>(
        adj, (long)N_ * N_, N_,
        support, (long)N_ * H_, H_, 0,
        out, (long)N_ * H_, H_, N_);

    stats_kernel<<<dim3(B_, H_ / 256), 256>>>(out);
    finalize_kernel<<<E_, H_>>>(bn_gamma, bn_beta);

    size_t total4 = (size_t)B_ * N_ * H_ / 4;
    bn_relu_kernel<<<(unsigned)(total4 / 256), 256>>>(out);
}

// round 4
// speedup vs baseline: 3.3116x; 1.5289x over previous
#include <cuda_runtime.h>
#include <cuda_fp16.h>
#include <cstdint>

#define B_ 64
#define N_ 512
#define H_ 1024
#define E_ 4
#define BN_EPS 1e-5f

// GEMM tile config: CTA 128x256, 8 warps of 64x64, BK=32, 4-stage cp.async
#define BM 128
#define BNG 256
#define BKK 32
#define GT 256
#define STAGES 4
#define STAGE_BYTES 40960   // A 8K | Bhi 16K | Blo 16K
#define OFF_BH 8192
#define OFF_BL 24576
#define SMEM_BYTES (STAGES * STAGE_BYTES)

// ---------------- scratch (static device globals; no allocation) ----------------
__device__ __align__(256) __half g_xh[(size_t)B_ * N_ * H_];
__device__ __align__(256) __half g_adjh[(size_t)B_ * N_ * N_];
__device__ __align__(256) __half g_wh_hi[(size_t)E_ * H_ * H_];
__device__ __align__(256) __half g_wh_lo[(size_t)E_ * H_ * H_];
__device__ __align__(256) __half g_sup_hi[(size_t)B_ * N_ * H_];
__device__ __align__(256) __half g_sup_lo[(size_t)B_ * N_ * H_];
__device__ __align__(256) float g_mean_part[B_ * 8 * H_];
__device__ __align__(256) float g_sum[E_ * H_];
__device__ __align__(256) float g_ss[E_ * H_];
__device__ __align__(256) float g_scale[E_ * H_];
__device__ __align__(256) float g_shift[E_ * H_];
__device__ int g_top1[B_];

// ---------------- PTX helpers (base-family ISA) ----------------
__device__ __forceinline__ uint32_t smem_u32(const void* p) {
    uint32_t a;
    asm("{ .reg .u64 t; cvta.to.shared.u64 t, %1; cvt.u32.u64 %0, t; }" : "=r"(a) : "l"(p));
    return a;
}
__device__ __forceinline__ void cp16(uint32_t d, const void* g) {
    asm volatile("cp.async.cg.shared.global [%0], [%1], 16;" :: "r"(d), "l"(g));
}
__device__ __forceinline__ void ldsm_x4(uint32_t (&r)[4], uint32_t addr) {
    asm volatile("ldmatrix.sync.aligned.m8n8.x4.shared.b16 {%0,%1,%2,%3}, [%4];"
        : "=r"(r[0]), "=r"(r[1]), "=r"(r[2]), "=r"(r[3]) : "r"(addr));
}
__device__ __forceinline__ void ldsm_x4_t(uint32_t (&r)[4], uint32_t addr) {
    asm volatile("ldmatrix.sync.aligned.m8n8.x4.trans.shared.b16 {%0,%1,%2,%3}, [%4];"
        : "=r"(r[0]), "=r"(r[1]), "=r"(r[2]), "=r"(r[3]) : "r"(addr));
}
__device__ __forceinline__ void mma_f16(float (&c)[4], const uint32_t (&a)[4], const uint32_t* b) {
    asm volatile(
        "mma.sync.aligned.m16n8k16.row.col.f32.f16.f16.f32 "
        "{%0,%1,%2,%3}, {%4,%5,%6,%7}, {%8,%9}, {%0,%1,%2,%3};"
        : "+f"(c[0]), "+f"(c[1]), "+f"(c[2]), "+f"(c[3])
        : "r"(a[0]), "r"(a[1]), "r"(a[2]), "r"(a[3]), "r"(b[0]), "r"(b[1]));
}

// ---------------- k0: zero accumulators ----------
__global__ void zero_stats_kernel() {
    int i = blockIdx.x * blockDim.x + threadIdx.x;
    if (i < E_ * H_) { g_sum[i] = 0.f; g_ss[i] = 0.f; }
}

// ---------------- k1: partial column means + x -> fp16 convert (fused) ----------
__global__ void mean_cvt_kernel(const float* __restrict__ x) {
    int b = blockIdx.x, s = blockIdx.y;
    size_t base = (size_t)b * N_ * H_ + (size_t)s * 64 * H_;
    const float* xb = x + base;
    __half* xh = g_xh + base;
    for (int h = threadIdx.x; h < H_; h += blockDim.x) {
        float acc = 0.f;
        #pragma unroll 8
        for (int n = 0; n < 64; n++) {
            float v = xb[(size_t)n * H_ + h];
            xh[(size_t)n * H_ + h] = __float2half_rn(v);
            acc += v;
        }
        g_mean_part[(b * 8 + s) * H_ + h] = acc;
    }
}

// ---------------- k2: router + argmax ----------
__global__ void router_kernel(const float* __restrict__ rw, const float* __restrict__ rb) {
    int b = blockIdx.x;
    __shared__ float sred[E_][256];
    float acc[E_] = {0.f, 0.f, 0.f, 0.f};
    for (int h = threadIdx.x; h < H_; h += 256) {
        float m = 0.f;
        #pragma unroll
        for (int s = 0; s < 8; s++) m += g_mean_part[(b * 8 + s) * H_ + h];
        m *= (1.0f / (float)N_);
        #pragma unroll
        for (int e = 0; e < E_; e++) acc[e] += m * rw[h * E_ + e];
    }
    #pragma unroll
    for (int e = 0; e < E_; e++) sred[e][threadIdx.x] = acc[e];
    __syncthreads();
    for (int off = 128; off > 0; off >>= 1) {
        if (threadIdx.x < off) {
            #pragma unroll
            for (int e = 0; e < E_; e++) sred[e][threadIdx.x] += sred[e][threadIdx.x + off];
        }
        __syncthreads();
    }
    if (threadIdx.x == 0) {
        int best = 0;
        float bv = sred[0][0] + rb[0];
        for (int e = 1; e < E_; e++) {
            float v = sred[e][0] + rb[e];
            if (v > bv) { bv = v; best = e; }
        }
        g_top1[b] = best;
    }
}

// ---------------- k3: adj -> fp16 (single) ----------
__global__ void cvt_adj_kernel(const float* __restrict__ src) {
    size_t i = ((size_t)blockIdx.x * blockDim.x + threadIdx.x) * 4;
    float4 v = *(const float4*)(src + i);
    __half2 h0 = __floats2half2_rn(v.x, v.y);
    __half2 h1 = __floats2half2_rn(v.z, v.w);
    *(__half2*)(g_adjh + i) = h0;
    *(__half2*)(g_adjh + i + 2) = h1;
}

// ---------------- k4: expert_w -> fp16 hi/lo ----------
__global__ void cvt_w_kernel(const float* __restrict__ src) {
    size_t i = ((size_t)blockIdx.x * blockDim.x + threadIdx.x) * 4;
    float4 v = *(const float4*)(src + i);
    __half hx = __float2half_rn(v.x), hy = __float2half_rn(v.y);
    __half hz = __float2half_rn(v.z), hw = __float2half_rn(v.w);
    *(__half2*)(g_wh_hi + i) = __halves2half2(hx, hy);
    *(__half2*)(g_wh_hi + i + 2) = __halves2half2(hz, hw);
    *(__half2*)(g_wh_lo + i) = __floats2half2_rn(v.x - __half2float(hx), v.y - __half2float(hy));
    *(__half2*)(g_wh_lo + i + 2) = __floats2half2_rn(v.z - __half2float(hz), v.w - __half2float(hw));
}

// ---------------- batched fp16 2-pass (B-corrected) mma GEMM ----------------
// C[bz](M x Nglob) = A[bz](MxK fp16) * (Bh + Bl)[sel](KxNglob fp16)
__global__ __launch_bounds__(GT, 1)
void gemm_f16_kernel(const __half* __restrict__ Abase, long strideA, int lda,
                     const __half* __restrict__ Bhbase, const __half* __restrict__ Blbase,
                     long strideB, int ldb, int useTop1,
                     float* __restrict__ Cf, __half* __restrict__ Chh, __half* __restrict__ Chl,
                     long strideC, int ldc, int K) {
    extern __shared__ __align__(128) char smem[];
    const uint32_t sb = smem_u32(smem);
    const int tid = threadIdx.x;
    const int lane = tid & 31, wid = tid >> 5;
    const int bz = blockIdx.z;
    const int m0 = blockIdx.y * BM, n0 = blockIdx.x * BNG;
    const int wm = (wid >> 2) * 64, wn = (wid & 3) * 64;

    const __half* A = Abase + (long)bz * strideA;
    const int sel = useTop1 ? g_top1[bz] : bz;
    const __half* Bh = Bhbase + (long)sel * strideB;
    const __half* Bl = Blbase + (long)sel * strideB;

    // cp.async roles
    const int ar = tid >> 1, ac0 = (tid & 1) * 2;      // A: row, chunk pair
    const int bk = tid >> 3, bn0 = (tid & 7) * 4;      // B: k row, chunk quad
    uint32_t a_off[2], b_off[4];
    #pragma unroll
    for (int q = 0; q < 2; q++) {
        int c = ac0 + q;
        a_off[q] = (uint32_t)(ar * 64 + ((c ^ ((ar >> 1) & 3)) << 4));
    }
    #pragma unroll
    for (int q = 0; q < 4; q++) {
        int nc = bn0 + q;
        b_off[q] = (uint32_t)((nc >> 4) * 8192 + bk * 256 + (((nc & 15) ^ (bk & 7)) << 4));
    }
    const __half* a_g = A + (long)(m0 + ar) * lda + ac0 * 8;
    const __half* bh_g = Bh + (long)bk * ldb + n0 + bn0 * 8;
    const __half* bl_g = Bl + (long)bk * ldb + n0 + bn0 * 8;

    float acc[4][8][4];
    #pragma unroll
    for (int a = 0; a < 4; a++)
        #pragma unroll
        for (int b2 = 0; b2 < 8; b2++)
            #pragma unroll
            for (int c = 0; c < 4; c++) acc[a][b2][c] = 0.f;

    auto issue = [&](int i) {
        uint32_t st = sb + (uint32_t)((i & (STAGES - 1)) * STAGE_BYTES);
        const __half* ag = a_g + (long)i * BKK;
        #pragma unroll
        for (int q = 0; q < 2; q++) cp16(st + a_off[q], ag + q * 8);
        const __half* bg = bh_g + (long)i * BKK * ldb;
        #pragma unroll
        for (int q = 0; q < 4; q++) cp16(st + OFF_BH + b_off[q], bg + q * 8);
        const __half* blg = bl_g + (long)i * BKK * ldb;
        #pragma unroll
        for (int q = 0; q < 4; q++) cp16(st + OFF_BL + b_off[q], blg + q * 8);
        asm volatile("cp.async.commit_group;" ::: "memory");
    };

    auto mma_tile = [&](int s) {
        const uint32_t aB = sb + (uint32_t)(s * STAGE_BYTES);
        #pragma unroll
        for (int ks = 0; ks < 2; ks++) {
            uint32_t ahf[4][4];
            #pragma unroll
            for (int mt = 0; mt < 4; mt++) {
                int r = wm + mt * 16 + (lane & 15);
                int c = ks * 2 + (lane >> 4);
                ldsm_x4(ahf[mt], aB + (uint32_t)(r * 64 + ((c ^ ((r >> 1) & 3)) << 4)));
            }
            int k = ks * 16 + (lane & 15);
            #pragma unroll
            for (int nt = 0; nt < 4; nt++) {
                int nl = wn + nt * 16 + ((lane >> 4) << 3);
                uint32_t boff = (uint32_t)((nl >> 7) * 8192 + k * 256 +
                                           ((((nl & 127) >> 3) ^ (k & 7)) << 4));
                uint32_t r4[4];
                ldsm_x4_t(r4, aB + OFF_BH + boff);
                #pragma unroll
                for (int mt = 0; mt < 4; mt++) {
                    mma_f16(acc[mt][nt * 2], ahf[mt], r4);
                    mma_f16(acc[mt][nt * 2 + 1], ahf[mt], r4 + 2);
                }
                ldsm_x4_t(r4, aB + OFF_BL + boff);
                #pragma unroll
                for (int mt = 0; mt < 4; mt++) {
                    mma_f16(acc[mt][nt * 2], ahf[mt], r4);
                    mma_f16(acc[mt][nt * 2 + 1], ahf[mt], r4 + 2);
                }
            }
        }
    };

    const int nk = K / BKK;
    issue(0); issue(1); issue(2);
    for (int i = 0; i < nk; i++) {
        asm volatile("cp.async.wait_group 2;" ::: "memory");
        __syncthreads();
        mma_tile(i & (STAGES - 1));
        if (i + 3 < nk) issue(i + 3);
        else asm volatile("cp.async.commit_group;" ::: "memory");
    }

    // epilogue
    if (Cf) {
        float* C = Cf + (long)bz * strideC;
        #pragma unroll
        for (int mt = 0; mt < 4; mt++) {
            int row0 = m0 + wm + mt * 16 + (lane >> 2);
            #pragma unroll
            for (int n8 = 0; n8 < 8; n8++) {
                int col = n0 + wn + n8 * 8 + (lane & 3) * 2;
                *(float2*)(C + (long)row0 * ldc + col) = make_float2(acc[mt][n8][0], acc[mt][n8][1]);
                *(float2*)(C + (long)(row0 + 8) * ldc + col) = make_float2(acc[mt][n8][2], acc[mt][n8][3]);
            }
        }
    } else {
        __half* CH = Chh + (long)bz * strideC;
        __half* CL = Chl + (long)bz * strideC;
        #pragma unroll
        for (int mt = 0; mt < 4; mt++) {
            int row0 = m0 + wm + mt * 16 + (lane >> 2);
            #pragma unroll
            for (int n8 = 0; n8 < 8; n8++) {
                int col = n0 + wn + n8 * 8 + (lane & 3) * 2;
                #pragma unroll
                for (int hrow = 0; hrow < 2; hrow++) {
                    float v0 = acc[mt][n8][hrow * 2], v1 = acc[mt][n8][hrow * 2 + 1];
                    __half h0 = __float2half_rn(v0), h1 = __float2half_rn(v1);
                    __half l0 = __float2half_rn(v0 - __half2float(h0));
                    __half l1 = __float2half_rn(v1 - __half2float(h1));
                    long off = (long)(row0 + hrow * 8) * ldc + col;
                    *(__half2*)(CH + off) = __halves2half2(h0, h1);
                    *(__half2*)(CL + off) = __halves2half2(l0, l1);
                }
            }
        }
    }
}

// ---------------- k5: per-expert BN statistics ----------
__global__ void stats_kernel(const float* __restrict__ out) {
    int b = blockIdx.x;
    int h = blockIdx.y * 256 + threadIdx.x;
    int e = g_top1[b];
    const float* ob = out + (size_t)b * N_ * H_ + h;
    float s = 0.f, ss = 0.f;
    #pragma unroll 4
    for (int n = 0; n < N_; n++) {
        float v = ob[(size_t)n * H_];
        s += v;
        ss += v * v;
    }
    atomicAdd(&g_sum[e * H_ + h], s);
    atomicAdd(&g_ss[e * H_ + h], ss);
}

// ---------------- k6: finalize BN scale/shift ----------
__global__ void finalize_kernel(const float* __restrict__ gamma, const float* __restrict__ beta) {
    int e = blockIdx.x, h = threadIdx.x;
    int cg = 0;
    for (int b = 0; b < B_; b++) cg += (g_top1[b] == e);
    float cnt = fmaxf((float)cg * (float)N_, 1.0f);
    float mean = g_sum[e * H_ + h] / cnt;
    float var = g_ss[e * H_ + h] / cnt - mean * mean;
    float inv = rsqrtf(var + BN_EPS);
    float sc = gamma[e * H_ + h] * inv;
    g_scale[e * H_ + h] = sc;
    g_shift[e * H_ + h] = beta[e * H_ + h] - mean * sc;
}

// ---------------- k7: apply BN + ReLU in place ----------
__global__ void bn_relu_kernel(float* __restrict__ out) {
    size_t idx = ((size_t)blockIdx.x * blockDim.x + threadIdx.x) * 4;
    int b = (int)(idx / ((size_t)N_ * H_));
    int h = (int)(idx % H_);
    int e = g_top1[b];
    float4 v = *(float4*)(out + idx);
    float4 sc = *(const float4*)&g_scale[e * H_ + h];
    float4 sh = *(const float4*)&g_shift[e * H_ + h];
    v.x = fmaxf(v.x * sc.x + sh.x, 0.f);
    v.y = fmaxf(v.y * sc.y + sh.y, 0.f);
    v.z = fmaxf(v.z * sc.z + sh.z, 0.f);
    v.w = fmaxf(v.w * sc.w + sh.w, 0.f);
    *(float4*)(out + idx) = v;
}

// ---------------- launcher ----------------
extern "C" void kernel_launch(void* const* d_in, const int* in_sizes, int n_in,
                              void* d_out, int out_size) {
    (void)in_sizes; (void)n_in; (void)out_size;
    const float* x        = (const float*)d_in[0];   // [B,N,H]
    const float* adj      = (const float*)d_in[1];   // [B,N,N]
    const float* router_w = (const float*)d_in[2];   // [H,E]
    const float* router_b = (const float*)d_in[3];   // [E]
    const float* expert_w = (const float*)d_in[4];   // [E,H,H]
    const float* bn_gamma = (const float*)d_in[5];   // [E,H]
    const float* bn_beta  = (const float*)d_in[6];   // [E,H]
    float* out = (float*)d_out;                      // [B,N,H]

    __half *xh, *adjh, *whh, *whl, *suph, *supl;
    cudaGetSymbolAddress((void**)&xh, g_xh);
    cudaGetSymbolAddress((void**)&adjh, g_adjh);
    cudaGetSymbolAddress((void**)&whh, g_wh_hi);
    cudaGetSymbolAddress((void**)&whl, g_wh_lo);
    cudaGetSymbolAddress((void**)&suph, g_sup_hi);
    cudaGetSymbolAddress((void**)&supl, g_sup_lo);

    cudaFuncSetAttribute(gemm_f16_kernel, cudaFuncAttributeMaxDynamicSharedMemorySize, SMEM_BYTES);

    zero_stats_kernel<<<16, 256>>>();
    mean_cvt_kernel<<<dim3(B_, 8), 256>>>(x);
    router_kernel<<<B_, 256>>>(router_w, router_b);
    cvt_adj_kernel<<<(unsigned)((size_t)B_ * N_ * N_ / 4 / 256), 256>>>(adj);
    cvt_w_kernel<<<(unsigned)((size_t)E_ * H_ * H_ / 4 / 256), 256>>>(expert_w);

    // support[b] = x[b] @ expert_w[top1[b]]  -> fp16 hi/lo
    gemm_f16_kernel<<<dim3(H_ / BNG, N_ / BM, B_), GT, SMEM_BYTES>>>(
        xh, (long)N_ * H_, H_,
        whh, whl, (long)H_ * H_, H_, 1,
        nullptr, suph, supl, (long)N_ * H_, H_, H_);

    // out[b] = adj[b] @ support[b]  -> fp32
    gemm_f16_kernel<<<dim3(H_ / BNG, N_ / BM, B_), GT, SMEM_BYTES>>>(
        adjh, (long)N_ * N_, N_,
        suph, supl, (long)N_ * H_, H_, 0,
        out, nullptr, nullptr, (long)N_ * H_, H_, N_);

    stats_kernel<<<dim3(B_, H_ / 256), 256>>>(out);
    finalize_kernel<<<E_, H_>>>(bn_gamma, bn_beta);

    size_t total4 = (size_t)B_ * N_ * H_ / 4;
    bn_relu_kernel<<<(unsigned)(total4 / 256), 256>>>(out);
}

// round 5
// speedup vs baseline: 5.2588x; 1.5880x over previous
#include <cuda_runtime.h>
#include <cuda_fp16.h>
#include <cstdint>

#define B_ 64
#define N_ 512
#define H_ 1024
#define E_ 4
#define BN_EPS 1e-5f

// GEMM tile config: CTA 128x256, 8 warps of 64x64, BK=32, 4-stage cp.async
#define BM 128
#define BNG 256
#define BKK 32
#define GT 256
#define STAGES 4
#define STAGE_BYTES 24576   // A 8K | B 16K
#define OFF_BH 8192
#define SMEM_BYTES (STAGES * STAGE_BYTES)

// ---------------- scratch (static device globals; no allocation) ----------------
__device__ __align__(256) __half g_xh[(size_t)B_ * N_ * H_];
__device__ __align__(256) __half g_adjh[(size_t)B_ * N_ * N_];
__device__ __align__(256) __half g_wh[(size_t)E_ * H_ * H_];
__device__ __align__(256) __half g_suph[(size_t)B_ * N_ * H_];
__device__ __align__(256) float g_mean_part[B_ * 8 * H_];
__device__ __align__(256) float g_sum[E_ * H_];
__device__ __align__(256) float g_ss[E_ * H_];
__device__ __align__(256) float g_scale[E_ * H_];
__device__ __align__(256) float g_shift[E_ * H_];
__device__ int g_top1[B_];

// ---------------- PTX helpers (base-family ISA) ----------------
__device__ __forceinline__ uint32_t smem_u32(const void* p) {
    uint32_t a;
    asm("{ .reg .u64 t; cvta.to.shared.u64 t, %1; cvt.u32.u64 %0, t; }" : "=r"(a) : "l"(p));
    return a;
}
__device__ __forceinline__ void cp16(uint32_t d, const void* g) {
    asm volatile("cp.async.cg.shared.global [%0], [%1], 16;" :: "r"(d), "l"(g));
}
__device__ __forceinline__ void ldsm_x4(uint32_t (&r)[4], uint32_t addr) {
    asm volatile("ldmatrix.sync.aligned.m8n8.x4.shared.b16 {%0,%1,%2,%3}, [%4];"
        : "=r"(r[0]), "=r"(r[1]), "=r"(r[2]), "=r"(r[3]) : "r"(addr));
}
__device__ __forceinline__ void ldsm_x4_t(uint32_t (&r)[4], uint32_t addr) {
    asm volatile("ldmatrix.sync.aligned.m8n8.x4.trans.shared.b16 {%0,%1,%2,%3}, [%4];"
        : "=r"(r[0]), "=r"(r[1]), "=r"(r[2]), "=r"(r[3]) : "r"(addr));
}
__device__ __forceinline__ void mma_f16(float (&c)[4], const uint32_t (&a)[4], const uint32_t* b) {
    asm volatile(
        "mma.sync.aligned.m16n8k16.row.col.f32.f16.f16.f32 "
        "{%0,%1,%2,%3}, {%4,%5,%6,%7}, {%8,%9}, {%0,%1,%2,%3};"
        : "+f"(c[0]), "+f"(c[1]), "+f"(c[2]), "+f"(c[3])
        : "r"(a[0]), "r"(a[1]), "r"(a[2]), "r"(a[3]), "r"(b[0]), "r"(b[1]));
}

// ---------------- k0: zero accumulators ----------
__global__ void zero_stats_kernel() {
    int i = blockIdx.x * blockDim.x + threadIdx.x;
    if (i < E_ * H_) { g_sum[i] = 0.f; g_ss[i] = 0.f; }
}

// ---------------- k1: partial column means + x -> fp16 convert (fused) ----------
__global__ void mean_cvt_kernel(const float* __restrict__ x) {
    int b = blockIdx.x, s = blockIdx.y;
    size_t base = (size_t)b * N_ * H_ + (size_t)s * 64 * H_;
    const float* xb = x + base;
    __half* xh = g_xh + base;
    for (int h = threadIdx.x; h < H_; h += blockDim.x) {
        float acc = 0.f;
        #pragma unroll 8
        for (int n = 0; n < 64; n++) {
            float v = xb[(size_t)n * H_ + h];
            xh[(size_t)n * H_ + h] = __float2half_rn(v);
            acc += v;
        }
        g_mean_part[(b * 8 + s) * H_ + h] = acc;
    }
}

// ---------------- k2: router + argmax ----------
__global__ void router_kernel(const float* __restrict__ rw, const float* __restrict__ rb) {
    int b = blockIdx.x;
    __shared__ float sred[E_][256];
    float acc[E_] = {0.f, 0.f, 0.f, 0.f};
    for (int h = threadIdx.x; h < H_; h += 256) {
        float m = 0.f;
        #pragma unroll
        for (int s = 0; s < 8; s++) m += g_mean_part[(b * 8 + s) * H_ + h];
        m *= (1.0f / (float)N_);
        #pragma unroll
        for (int e = 0; e < E_; e++) acc[e] += m * rw[h * E_ + e];
    }
    #pragma unroll
    for (int e = 0; e < E_; e++) sred[e][threadIdx.x] = acc[e];
    __syncthreads();
    for (int off = 128; off > 0; off >>= 1) {
        if (threadIdx.x < off) {
            #pragma unroll
            for (int e = 0; e < E_; e++) sred[e][threadIdx.x] += sred[e][threadIdx.x + off];
        }
        __syncthreads();
    }
    if (threadIdx.x == 0) {
        int best = 0;
        float bv = sred[0][0] + rb[0];
        for (int e = 1; e < E_; e++) {
            float v = sred[e][0] + rb[e];
            if (v > bv) { bv = v; best = e; }
        }
        g_top1[b] = best;
    }
}

// ---------------- k3: adj -> fp16 ----------
__global__ void cvt_adj_kernel(const float* __restrict__ src) {
    size_t i = ((size_t)blockIdx.x * blockDim.x + threadIdx.x) * 4;
    float4 v = *(const float4*)(src + i);
    *(__half2*)(g_adjh + i) = __floats2half2_rn(v.x, v.y);
    *(__half2*)(g_adjh + i + 2) = __floats2half2_rn(v.z, v.w);
}

// ---------------- k4: expert_w -> fp16 ----------
__global__ void cvt_w_kernel(const float* __restrict__ src) {
    size_t i = ((size_t)blockIdx.x * blockDim.x + threadIdx.x) * 4;
    float4 v = *(const float4*)(src + i);
    *(__half2*)(g_wh + i) = __floats2half2_rn(v.x, v.y);
    *(__half2*)(g_wh + i + 2) = __floats2half2_rn(v.z, v.w);
}

// ---------------- batched fp16 single-pass mma GEMM ----------------
// C[bz](M x Nglob) = A[bz](MxK fp16) * B[sel](KxNglob fp16)
// Cf != null : fp32 output + fused BN statistics (atomics)
// Cf == null : fp16 output
__global__ __launch_bounds__(GT, 1)
void gemm_f16_kernel(const __half* __restrict__ Abase, long strideA, int lda,
                     const __half* __restrict__ Bbase, long strideB, int ldb, int useTop1,
                     float* __restrict__ Cf, __half* __restrict__ Ch,
                     long strideC, int ldc, int K) {
    extern __shared__ __align__(128) char smem[];
    const uint32_t sb = smem_u32(smem);
    const int tid = threadIdx.x;
    const int lane = tid & 31, wid = tid >> 5;
    const int bz = blockIdx.z;
    const int m0 = blockIdx.y * BM, n0 = blockIdx.x * BNG;
    const int wm = (wid >> 2) * 64, wn = (wid & 3) * 64;

    const __half* A = Abase + (long)bz * strideA;
    const int sel = useTop1 ? g_top1[bz] : bz;
    const __half* Bg = Bbase + (long)sel * strideB;

    // cp.async roles
    const int ar = tid >> 1, ac0 = (tid & 1) * 2;      // A: row, chunk pair
    const int bk = tid >> 3, bn0 = (tid & 7) * 4;      // B: k row, chunk quad
    uint32_t a_off[2], b_off[4];
    #pragma unroll
    for (int q = 0; q < 2; q++) {
        int c = ac0 + q;
        a_off[q] = (uint32_t)(ar * 64 + ((c ^ ((ar >> 1) & 3)) << 4));
    }
    #pragma unroll
    for (int q = 0; q < 4; q++) {
        int nc = bn0 + q;
        b_off[q] = (uint32_t)((nc >> 4) * 8192 + bk * 256 + (((nc & 15) ^ (bk & 7)) << 4));
    }
    const __half* a_g = A + (long)(m0 + ar) * lda + ac0 * 8;
    const __half* b_g = Bg + (long)bk * ldb + n0 + bn0 * 8;

    float acc[4][8][4];
    #pragma unroll
    for (int a = 0; a < 4; a++)
        #pragma unroll
        for (int b2 = 0; b2 < 8; b2++)
            #pragma unroll
            for (int c = 0; c < 4; c++) acc[a][b2][c] = 0.f;

    auto issue = [&](int i) {
        uint32_t st = sb + (uint32_t)((i & (STAGES - 1)) * STAGE_BYTES);
        const __half* ag = a_g + (long)i * BKK;
        #pragma unroll
        for (int q = 0; q < 2; q++) cp16(st + a_off[q], ag + q * 8);
        const __half* bg = b_g + (long)i * BKK * ldb;
        #pragma unroll
        for (int q = 0; q < 4; q++) cp16(st + OFF_BH + b_off[q], bg + q * 8);
        asm volatile("cp.async.commit_group;" ::: "memory");
    };

    auto mma_tile = [&](int s) {
        const uint32_t aB = sb + (uint32_t)(s * STAGE_BYTES);
        #pragma unroll
        for (int ks = 0; ks < 2; ks++) {
            uint32_t ahf[4][4];
            #pragma unroll
            for (int mt = 0; mt < 4; mt++) {
                int r = wm + mt * 16 + (lane & 15);
                int c = ks * 2 + (lane >> 4);
                ldsm_x4(ahf[mt], aB + (uint32_t)(r * 64 + ((c ^ ((r >> 1) & 3)) << 4)));
            }
            int k = ks * 16 + (lane & 15);
            #pragma unroll
            for (int nt = 0; nt < 4; nt++) {
                int nl = wn + nt * 16 + ((lane >> 4) << 3);
                uint32_t boff = (uint32_t)((nl >> 7) * 8192 + k * 256 +
                                           ((((nl & 127) >> 3) ^ (k & 7)) << 4));
                uint32_t r4[4];
                ldsm_x4_t(r4, aB + OFF_BH + boff);
                #pragma unroll
                for (int mt = 0; mt < 4; mt++) {
                    mma_f16(acc[mt][nt * 2], ahf[mt], r4);
                    mma_f16(acc[mt][nt * 2 + 1], ahf[mt], r4 + 2);
                }
            }
        }
    };

    const int nk = K / BKK;
    issue(0); issue(1); issue(2);
    for (int i = 0; i < nk; i++) {
        asm volatile("cp.async.wait_group 2;" ::: "memory");
        __syncthreads();
        mma_tile(i & (STAGES - 1));
        if (i + 3 < nk) issue(i + 3);
        else asm volatile("cp.async.commit_group;" ::: "memory");
    }

    // epilogue
    if (Cf) {
        float* C = Cf + (long)bz * strideC;
        #pragma unroll
        for (int mt = 0; mt < 4; mt++) {
            int row0 = m0 + wm + mt * 16 + (lane >> 2);
            #pragma unroll
            for (int n8 = 0; n8 < 8; n8++) {
                int col = n0 + wn + n8 * 8 + (lane & 3) * 2;
                *(float2*)(C + (long)row0 * ldc + col) = make_float2(acc[mt][n8][0], acc[mt][n8][1]);
                *(float2*)(C + (long)(row0 + 8) * ldc + col) = make_float2(acc[mt][n8][2], acc[mt][n8][3]);
            }
        }
        // fused per-expert BN statistics
        int e = g_top1[bz];
        #pragma unroll
        for (int n8 = 0; n8 < 8; n8++) {
            #pragma unroll
            for (int c2 = 0; c2 < 2; c2++) {
                float s = 0.f, q = 0.f;
                #pragma unroll
                for (int mt = 0; mt < 4; mt++) {
                    float v0 = acc[mt][n8][c2], v1 = acc[mt][n8][c2 + 2];
                    s += v0 + v1;
                    q += v0 * v0 + v1 * v1;
                }
                s += __shfl_xor_sync(0xFFFFFFFFu, s, 4);
                q += __shfl_xor_sync(0xFFFFFFFFu, q, 4);
                s += __shfl_xor_sync(0xFFFFFFFFu, s, 8);
                q += __shfl_xor_sync(0xFFFFFFFFu, q, 8);
                s += __shfl_xor_sync(0xFFFFFFFFu, s, 16);
                q += __shfl_xor_sync(0xFFFFFFFFu, q, 16);
                if ((lane >> 2) == 0) {
                    int col = n0 + wn + n8 * 8 + (lane & 3) * 2 + c2;
                    atomicAdd(&g_sum[e * H_ + col], s);
                    atomicAdd(&g_ss[e * H_ + col], q);
                }
            }
        }
    } else {
        __half* CH = Ch + (long)bz * strideC;
        #pragma unroll
        for (int mt = 0; mt < 4; mt++) {
            int row0 = m0 + wm + mt * 16 + (lane >> 2);
            #pragma unroll
            for (int n8 = 0; n8 < 8; n8++) {
                int col = n0 + wn + n8 * 8 + (lane & 3) * 2;
                *(__half2*)(CH + (long)row0 * ldc + col) =
                    __floats2half2_rn(acc[mt][n8][0], acc[mt][n8][1]);
                *(__half2*)(CH + (long)(row0 + 8) * ldc + col) =
                    __floats2half2_rn(acc[mt][n8][2], acc[mt][n8][3]);
            }
        }
    }
}

// ---------------- k6: finalize BN scale/shift ----------
__global__ void finalize_kernel(const float* __restrict__ gamma, const float* __restrict__ beta) {
    int e = blockIdx.x, h = threadIdx.x;
    int cg = 0;
    for (int b = 0; b < B_; b++) cg += (g_top1[b] == e);
    float cnt = fmaxf((float)cg * (float)N_, 1.0f);
    float mean = g_sum[e * H_ + h] / cnt;
    float var = g_ss[e * H_ + h] / cnt - mean * mean;
    float inv = rsqrtf(var + BN_EPS);
    float sc = gamma[e * H_ + h] * inv;
    g_scale[e * H_ + h] = sc;
    g_shift[e * H_ + h] = beta[e * H_ + h] - mean * sc;
}

// ---------------- k7: apply BN + ReLU in place ----------
__global__ void bn_relu_kernel(float* __restrict__ out) {
    size_t idx = ((size_t)blockIdx.x * blockDim.x + threadIdx.x) * 4;
    int b = (int)(idx / ((size_t)N_ * H_));
    int h = (int)(idx % H_);
    int e = g_top1[b];
    float4 v = *(float4*)(out + idx);
    float4 sc = *(const float4*)&g_scale[e * H_ + h];
    float4 sh = *(const float4*)&g_shift[e * H_ + h];
    v.x = fmaxf(v.x * sc.x + sh.x, 0.f);
    v.y = fmaxf(v.y * sc.y + sh.y, 0.f);
    v.z = fmaxf(v.z * sc.z + sh.z, 0.f);
    v.w = fmaxf(v.w * sc.w + sh.w, 0.f);
    *(float4*)(out + idx) = v;
}

// ---------------- launcher ----------------
extern "C" void kernel_launch(void* const* d_in, const int* in_sizes, int n_in,
                              void* d_out, int out_size) {
    (void)in_sizes; (void)n_in; (void)out_size;
    const float* x        = (const float*)d_in[0];   // [B,N,H]
    const float* adj      = (const float*)d_in[1];   // [B,N,N]
    const float* router_w = (const float*)d_in[2];   // [H,E]
    const float* router_b = (const float*)d_in[3];   // [E]
    const float* expert_w = (const float*)d_in[4];   // [E,H,H]
    const float* bn_gamma = (const float*)d_in[5];   // [E,H]
    const float* bn_beta  = (const float*)d_in[6];   // [E,H]
    float* out = (float*)d_out;                      // [B,N,H]

    __half *xh, *adjh, *wh, *suph;
    cudaGetSymbolAddress((void**)&xh, g_xh);
    cudaGetSymbolAddress((void**)&adjh, g_adjh);
    cudaGetSymbolAddress((void**)&wh, g_wh);
    cudaGetSymbolAddress((void**)&suph, g_suph);

    cudaFuncSetAttribute(gemm_f16_kernel, cudaFuncAttributeMaxDynamicSharedMemorySize, SMEM_BYTES);

    zero_stats_kernel<<<16, 256>>>();
    mean_cvt_kernel<<<dim3(B_, 8), 256>>>(x);
    router_kernel<<<B_, 256>>>(router_w, router_b);
    cvt_adj_kernel<<<(unsigned)((size_t)B_ * N_ * N_ / 4 / 256), 256>>>(adj);
    cvt_w_kernel<<<(unsigned)((size_t)E_ * H_ * H_ / 4 / 256), 256>>>(expert_w);

    // support[b] = x[b] @ expert_w[top1[b]]  -> fp16
    gemm_f16_kernel<<<dim3(H_ / BNG, N_ / BM, B_), GT, SMEM_BYTES>>>(
        xh, (long)N_ * H_, H_,
        wh, (long)H_ * H_, H_, 1,
        nullptr, suph, (long)N_ * H_, H_, H_);

    // out[b] = adj[b] @ support[b]  -> fp32 + fused stats
    gemm_f16_kernel<<<dim3(H_ / BNG, N_ / BM, B_), GT, SMEM_BYTES>>>(
        adjh, (long)N_ * N_, N_,
        suph, (long)N_ * H_, H_, 0,
        out, nullptr, (long)N_ * H_, H_, N_);

    finalize_kernel<<<E_, H_>>>(bn_gamma, bn_beta);

    size_t total4 = (size_t)B_ * N_ * H_ / 4;
    bn_relu_kernel<<<(unsigned)(total4 / 256), 256>>>(out);
}